// round 1
// baseline (speedup 1.0000x reference)
#include <cuda_runtime.h>
#include <cuda_bf16.h>
#include <math.h>

// Problem constants
#define M_BATCH   32
#define D_FEAT    256
#define HW        3136            // 56*56
#define NGRP      16
#define GS        16
#define NPOS      (M_BATCH * HW)  // 100352 samples per channel
#define PAIRS     136             // 16*17/2 lower-triangular entries
#define EPS_W     1e-6f

// Scratch (no allocations allowed)
__device__ float g_sum[NGRP][GS];        // per-channel sums
__device__ float g_prod[NGRP][PAIRS];    // per-group Gram (lower tri)
__device__ float g_W[NGRP][GS * GS];     // whitening matrices (full 16x16, zero upper)
__device__ float g_mu[NGRP][GS];         // per-channel means

// ---------------------------------------------------------------------------
// Kernel 0: zero the accumulators (must run every launch for determinism)
// ---------------------------------------------------------------------------
__global__ void zero_kernel() {
    int t = threadIdx.x;
    float* s = (float*)g_sum;   // 256 floats
    float* p = (float*)g_prod;  // 2176 floats
    for (int i = t; i < NGRP * GS; i += 256) s[i] = 0.0f;
    for (int i = t; i < NGRP * PAIRS; i += 256) p[i] = 0.0f;
}

// ---------------------------------------------------------------------------
// Kernel 1: per-group sums + Gram matrix in one pass over x
// grid = (NGRP, BY), block = 256
// ---------------------------------------------------------------------------
__global__ void __launch_bounds__(256) stats_kernel(const float* __restrict__ x) {
    const int g   = blockIdx.x;
    const int tid = threadIdx.x;
    const int nthr = gridDim.y * 256;
    const int gt   = blockIdx.y * 256 + tid;

    float s[GS];
    float p[PAIRS];
#pragma unroll
    for (int i = 0; i < GS; i++) s[i] = 0.0f;
#pragma unroll
    for (int i = 0; i < PAIRS; i++) p[i] = 0.0f;

    const float* xg = x + (size_t)g * GS * HW;  // start of group's channels for m=0

    for (int pos = gt; pos < NPOS; pos += nthr) {
        int m  = pos / HW;
        int hw = pos - m * HW;
        const float* b = xg + (size_t)m * (D_FEAT * HW) + hw;
        float v[GS];
#pragma unroll
        for (int c = 0; c < GS; c++) v[c] = b[(size_t)c * HW];
#pragma unroll
        for (int c = 0; c < GS; c++) s[c] += v[c];
        int k = 0;
#pragma unroll
        for (int i = 0; i < GS; i++)
#pragma unroll
            for (int j = 0; j <= i; j++) {
                p[k] += v[i] * v[j];
                k++;
            }
    }

    // --- block reduction: warp shuffle tree -> shared atomics -> global atomics
    __shared__ float rs[GS + PAIRS];
    for (int i = tid; i < GS + PAIRS; i += 256) rs[i] = 0.0f;
    __syncthreads();

    const int lane = tid & 31;
#pragma unroll
    for (int i = 0; i < GS; i++) {
        float v = s[i];
        v += __shfl_down_sync(0xffffffffu, v, 16);
        v += __shfl_down_sync(0xffffffffu, v, 8);
        v += __shfl_down_sync(0xffffffffu, v, 4);
        v += __shfl_down_sync(0xffffffffu, v, 2);
        v += __shfl_down_sync(0xffffffffu, v, 1);
        if (lane == 0) atomicAdd(&rs[i], v);
    }
#pragma unroll
    for (int k = 0; k < PAIRS; k++) {
        float v = p[k];
        v += __shfl_down_sync(0xffffffffu, v, 16);
        v += __shfl_down_sync(0xffffffffu, v, 8);
        v += __shfl_down_sync(0xffffffffu, v, 4);
        v += __shfl_down_sync(0xffffffffu, v, 2);
        v += __shfl_down_sync(0xffffffffu, v, 1);
        if (lane == 0) atomicAdd(&rs[GS + k], v);
    }
    __syncthreads();

    for (int i = tid; i < GS + PAIRS; i += 256) {
        float v = rs[i];
        if (i < GS) atomicAdd(&g_sum[g][i], v);
        else        atomicAdd(&g_prod[g][i - GS], v);
    }
}

// ---------------------------------------------------------------------------
// Kernel 2: build sigma, Cholesky, invert lower-triangular. One thread/group.
// Fully unrolled so everything lives in registers.
// ---------------------------------------------------------------------------
__global__ void solve_kernel() {
    const int g = threadIdx.x;
    if (g >= NGRP) return;

    const float n  = (float)NPOS;
    const float nm1 = (float)(NPOS - 1);

    float mu[GS];
#pragma unroll
    for (int c = 0; c < GS; c++) mu[c] = g_sum[g][c] / n;

    // sigma (lower triangle, linear index k = i*(i+1)/2 + j)
    float a[PAIRS];
#pragma unroll
    for (int i = 0; i < GS; i++)
#pragma unroll
        for (int j = 0; j <= i; j++) {
            const int k = i * (i + 1) / 2 + j;
            float cv = (g_prod[g][k] - n * mu[i] * mu[j]) / nm1;
            cv *= (1.0f - EPS_W);
            if (i == j) cv += EPS_W;
            a[k] = cv;
        }

    // Cholesky in place (lower)
#pragma unroll
    for (int j = 0; j < GS; j++) {
        float d = a[j * (j + 1) / 2 + j];
#pragma unroll
        for (int k = 0; k < j; k++) {
            float t = a[j * (j + 1) / 2 + k];
            d -= t * t;
        }
        d = sqrtf(d);
        a[j * (j + 1) / 2 + j] = d;
        const float inv = 1.0f / d;
#pragma unroll
        for (int i = j + 1; i < GS; i++) {
            float s2 = a[i * (i + 1) / 2 + j];
#pragma unroll
            for (int k = 0; k < j; k++)
                s2 -= a[i * (i + 1) / 2 + k] * a[j * (j + 1) / 2 + k];
            a[i * (i + 1) / 2 + j] = s2 * inv;
        }
    }

    // In-place inverse of lower-triangular T (ascending columns is safe:
    // t[i][k] for k>j is overwritten only at its own column k>j, later)
#pragma unroll
    for (int j = 0; j < GS; j++) {
        a[j * (j + 1) / 2 + j] = 1.0f / a[j * (j + 1) / 2 + j];  // w[j][j]
#pragma unroll
        for (int i = j + 1; i < GS; i++) {
            float s2 = 0.0f;
#pragma unroll
            for (int k = j; k < i; k++)
                s2 += a[i * (i + 1) / 2 + k] * a[k * (k + 1) / 2 + j];
            a[i * (i + 1) / 2 + j] = -s2 / a[i * (i + 1) / 2 + i];
        }
    }

    // Write out W (full matrix, zero upper) and mu
#pragma unroll
    for (int i = 0; i < GS; i++)
#pragma unroll
        for (int j = 0; j < GS; j++)
            g_W[g][i * GS + j] = (j <= i) ? a[i * (i + 1) / 2 + j] : 0.0f;
#pragma unroll
    for (int c = 0; c < GS; c++) g_mu[g][c] = mu[c];
}

// ---------------------------------------------------------------------------
// Kernel 3: apply whitening, float4-vectorized over spatial dim
// grid = (NGRP, BY), block = 256
// ---------------------------------------------------------------------------
#define HW4   (HW / 4)     // 784
#define NPOS4 (NPOS / 4)   // 25088

__global__ void __launch_bounds__(256) apply_kernel(const float* __restrict__ x,
                                                    float* __restrict__ out) {
    const int g   = blockIdx.x;
    const int tid = threadIdx.x;

    __shared__ float Ws[GS * GS];
    __shared__ float mus[GS];
    Ws[tid & 255] = g_W[g][tid & 255];        // blockDim == 256
    if (tid < GS) mus[tid] = g_mu[g][tid];
    __syncthreads();

    const float4* x4 = (const float4*)x;
    float4*       o4 = (float4*)out;
    const int nthr = gridDim.y * 256;

    for (int pos = blockIdx.y * 256 + tid; pos < NPOS4; pos += nthr) {
        int m = pos / HW4;
        int q = pos - m * HW4;
        size_t base = ((size_t)m * D_FEAT + (size_t)g * GS) * HW4 + q;

        float4 v[GS];
#pragma unroll
        for (int c = 0; c < GS; c++) {
            float4 t = x4[base + (size_t)c * HW4];
            float mc = mus[c];
            t.x -= mc; t.y -= mc; t.z -= mc; t.w -= mc;
            v[c] = t;
        }
#pragma unroll
        for (int c = 0; c < GS; c++) {
            float4 acc = make_float4(0.0f, 0.0f, 0.0f, 0.0f);
#pragma unroll
            for (int j = 0; j <= c; j++) {
                float w = Ws[c * GS + j];
                acc.x += w * v[j].x;
                acc.y += w * v[j].y;
                acc.z += w * v[j].z;
                acc.w += w * v[j].w;
            }
            o4[base + (size_t)c * HW4] = acc;
        }
    }
}

// ---------------------------------------------------------------------------
extern "C" void kernel_launch(void* const* d_in, const int* in_sizes, int n_in,
                              void* d_out, int out_size) {
    const float* x = (const float*)d_in[0];
    float* out = (float*)d_out;

    zero_kernel<<<1, 256>>>();
    stats_kernel<<<dim3(NGRP, 9), 256>>>(x);
    solve_kernel<<<1, 32>>>();
    apply_kernel<<<dim3(NGRP, 37), 256>>>(x, out);
}

// round 2
// speedup vs baseline: 1.1452x; 1.1452x over previous
#include <cuda_runtime.h>
#include <cuda_bf16.h>
#include <math.h>

// Problem constants
#define M_BATCH   32
#define D_FEAT    256
#define HW        3136            // 56*56
#define HW2       (HW/2)          // 1568 (float2 units)
#define HW4       (HW/4)          // 784  (float4 units)
#define NGRP      16
#define GS        16
#define NPOS      (M_BATCH * HW)  // 100352
#define NPOS2     (NPOS/2)        // 50176
#define NPOS4     (NPOS/4)        // 25088
#define PAIRS     136
#define EPS_W     1e-6f

#define STATS_BY  18
#define APPLY_BY  18

// Scratch
__device__ float g_sum[NGRP][GS];
__device__ float g_prod[NGRP][PAIRS];
__device__ float g_W[NGRP][GS * GS];
__device__ float g_b[NGRP][GS];          // W * mu  (bias fold)

// ---------------------------------------------------------------------------
__global__ void zero_kernel() {
    int t = threadIdx.x;
    float* s = (float*)g_sum;
    float* p = (float*)g_prod;
    for (int i = t; i < NGRP * GS; i += 256) s[i] = 0.0f;
    for (int i = t; i < NGRP * PAIRS; i += 256) p[i] = 0.0f;
}

// ---------------------------------------------------------------------------
// stats: role-split Gram. Block = 256 thr. grid = (NGRP, STATS_BY).
//   warps 0-1 (64 slices): role A  = lower-tri of ch 0-7   (36 acc) + sums 0-7
//   warps 2-5 (128 slices): role B = ch 8-15 x ch 0-7      (64 acc)
//   warps 6-7 (64 slices): role C  = lower-tri of ch 8-15  (36 acc) + sums 8-15
// Every role sweeps every float2-position of the block's contiguous chunk.
// ---------------------------------------------------------------------------
__global__ void __launch_bounds__(256, 2) stats_kernel(const float* __restrict__ x) {
    const int g   = blockIdx.x;
    const int tid = threadIdx.x;
    const int wid = tid >> 5;

    // contiguous chunk of float2-positions for this blockIdx.y
    const int CHUNK = (NPOS2 + STATS_BY - 1) / STATS_BY;   // 2788
    const int P0 = blockIdx.y * CHUNK;
    int P1 = P0 + CHUNK; if (P1 > NPOS2) P1 = NPOS2;

    const float2* x2 = (const float2*)x;
    const size_t gbase = (size_t)g * GS * HW2;   // offset of group's ch 0 within one m

    __shared__ float rsum[GS];
    __shared__ float rpair[PAIRS];
    for (int i = tid; i < GS; i += 256) rsum[i] = 0.0f;
    for (int i = tid; i < PAIRS; i += 256) rpair[i] = 0.0f;
    __syncthreads();

    const int lane = tid & 31;

    if (wid < 2) {
        // ---- role A: channels 0-7 ----
        float acc[36], s[8];
#pragma unroll
        for (int i = 0; i < 36; i++) acc[i] = 0.0f;
#pragma unroll
        for (int i = 0; i < 8; i++) s[i] = 0.0f;

        for (int p2 = P0 + tid; p2 < P1; p2 += 64) {
            const int m   = p2 / HW2;
            const int hw2 = p2 - m * HW2;
            const float2* b = x2 + (size_t)m * (D_FEAT * HW2) + gbase + hw2;
            float2 v[8];
#pragma unroll
            for (int c = 0; c < 8; c++) v[c] = b[(size_t)c * HW2];
#pragma unroll
            for (int c = 0; c < 8; c++) { s[c] += v[c].x; s[c] += v[c].y; }
            int k = 0;
#pragma unroll
            for (int i = 0; i < 8; i++)
#pragma unroll
                for (int j = 0; j <= i; j++) {
                    acc[k] += v[i].x * v[j].x;
                    acc[k] += v[i].y * v[j].y;
                    k++;
                }
        }
        // warp reduce -> shared
#pragma unroll
        for (int k = 0; k < 36; k++) {
            float v = acc[k];
            v += __shfl_down_sync(0xffffffffu, v, 16);
            v += __shfl_down_sync(0xffffffffu, v, 8);
            v += __shfl_down_sync(0xffffffffu, v, 4);
            v += __shfl_down_sync(0xffffffffu, v, 2);
            v += __shfl_down_sync(0xffffffffu, v, 1);
            if (lane == 0) {
                // linear index for (i,j), i<8: i*(i+1)/2 + j == k directly
                atomicAdd(&rpair[k], v);
            }
        }
#pragma unroll
        for (int c = 0; c < 8; c++) {
            float v = s[c];
            v += __shfl_down_sync(0xffffffffu, v, 16);
            v += __shfl_down_sync(0xffffffffu, v, 8);
            v += __shfl_down_sync(0xffffffffu, v, 4);
            v += __shfl_down_sync(0xffffffffu, v, 2);
            v += __shfl_down_sync(0xffffffffu, v, 1);
            if (lane == 0) atomicAdd(&rsum[c], v);
        }
    } else if (wid < 6) {
        // ---- role B: rows 8-15 x cols 0-7 (full 8x8) ----
        float acc[64];
#pragma unroll
        for (int i = 0; i < 64; i++) acc[i] = 0.0f;
        const int slice = tid - 64;            // 0..127

        for (int p2 = P0 + slice; p2 < P1; p2 += 128) {
            const int m   = p2 / HW2;
            const int hw2 = p2 - m * HW2;
            const float2* b = x2 + (size_t)m * (D_FEAT * HW2) + gbase + hw2;
            float2 vl[8], vh[8];
#pragma unroll
            for (int c = 0; c < 8; c++) vl[c] = b[(size_t)c * HW2];
#pragma unroll
            for (int c = 0; c < 8; c++) vh[c] = b[(size_t)(c + 8) * HW2];
#pragma unroll
            for (int i = 0; i < 8; i++)
#pragma unroll
                for (int j = 0; j < 8; j++) {
                    acc[i * 8 + j] += vh[i].x * vl[j].x;
                    acc[i * 8 + j] += vh[i].y * vl[j].y;
                }
        }
#pragma unroll
        for (int i = 0; i < 8; i++)
#pragma unroll
            for (int j = 0; j < 8; j++) {
                float v = acc[i * 8 + j];
                v += __shfl_down_sync(0xffffffffu, v, 16);
                v += __shfl_down_sync(0xffffffffu, v, 8);
                v += __shfl_down_sync(0xffffffffu, v, 4);
                v += __shfl_down_sync(0xffffffffu, v, 2);
                v += __shfl_down_sync(0xffffffffu, v, 1);
                if (lane == 0) {
                    const int r = i + 8;
                    atomicAdd(&rpair[r * (r + 1) / 2 + j], v);
                }
            }
    } else {
        // ---- role C: channels 8-15 lower-tri ----
        float acc[36], s[8];
#pragma unroll
        for (int i = 0; i < 36; i++) acc[i] = 0.0f;
#pragma unroll
        for (int i = 0; i < 8; i++) s[i] = 0.0f;
        const int slice = tid - 192;           // 0..63

        for (int p2 = P0 + slice; p2 < P1; p2 += 64) {
            const int m   = p2 / HW2;
            const int hw2 = p2 - m * HW2;
            const float2* b = x2 + (size_t)m * (D_FEAT * HW2) + gbase + hw2;
            float2 v[8];
#pragma unroll
            for (int c = 0; c < 8; c++) v[c] = b[(size_t)(c + 8) * HW2];
#pragma unroll
            for (int c = 0; c < 8; c++) { s[c] += v[c].x; s[c] += v[c].y; }
            int k = 0;
#pragma unroll
            for (int i = 0; i < 8; i++)
#pragma unroll
                for (int j = 0; j <= i; j++) {
                    acc[k] += v[i].x * v[j].x;
                    acc[k] += v[i].y * v[j].y;
                    k++;
                }
        }
        int k = 0;
#pragma unroll
        for (int i = 0; i < 8; i++)
#pragma unroll
            for (int j = 0; j <= i; j++) {
                float v = acc[k];
                v += __shfl_down_sync(0xffffffffu, v, 16);
                v += __shfl_down_sync(0xffffffffu, v, 8);
                v += __shfl_down_sync(0xffffffffu, v, 4);
                v += __shfl_down_sync(0xffffffffu, v, 2);
                v += __shfl_down_sync(0xffffffffu, v, 1);
                if (lane == 0) {
                    const int r = i + 8, c2 = j + 8;
                    atomicAdd(&rpair[r * (r + 1) / 2 + c2], v);
                }
                k++;
            }
#pragma unroll
        for (int c = 0; c < 8; c++) {
            float v = s[c];
            v += __shfl_down_sync(0xffffffffu, v, 16);
            v += __shfl_down_sync(0xffffffffu, v, 8);
            v += __shfl_down_sync(0xffffffffu, v, 4);
            v += __shfl_down_sync(0xffffffffu, v, 2);
            v += __shfl_down_sync(0xffffffffu, v, 1);
            if (lane == 0) atomicAdd(&rsum[c + 8], v);
        }
    }
    __syncthreads();

    // block -> global
    for (int i = tid; i < GS + PAIRS; i += 256) {
        if (i < GS) atomicAdd(&g_sum[g][i], rsum[i]);
        else        atomicAdd(&g_prod[g][i - GS], rpair[i - GS]);
    }
}

// ---------------------------------------------------------------------------
// solve: sigma -> Cholesky -> inv(T) -> W, b = W*mu. One thread per group.
// ---------------------------------------------------------------------------
__global__ void solve_kernel() {
    const int g = threadIdx.x;
    if (g >= NGRP) return;

    const float n   = (float)NPOS;
    const float nm1 = (float)(NPOS - 1);

    float mu[GS];
#pragma unroll
    for (int c = 0; c < GS; c++) mu[c] = g_sum[g][c] / n;

    float a[PAIRS];
#pragma unroll
    for (int i = 0; i < GS; i++)
#pragma unroll
        for (int j = 0; j <= i; j++) {
            const int k = i * (i + 1) / 2 + j;
            float cv = (g_prod[g][k] - n * mu[i] * mu[j]) / nm1;
            cv *= (1.0f - EPS_W);
            if (i == j) cv += EPS_W;
            a[k] = cv;
        }

    // Cholesky (lower, in place)
#pragma unroll
    for (int j = 0; j < GS; j++) {
        float d = a[j * (j + 1) / 2 + j];
#pragma unroll
        for (int k = 0; k < j; k++) {
            float t = a[j * (j + 1) / 2 + k];
            d -= t * t;
        }
        d = sqrtf(d);
        a[j * (j + 1) / 2 + j] = d;
        const float inv = 1.0f / d;
#pragma unroll
        for (int i = j + 1; i < GS; i++) {
            float s2 = a[i * (i + 1) / 2 + j];
#pragma unroll
            for (int k = 0; k < j; k++)
                s2 -= a[i * (i + 1) / 2 + k] * a[j * (j + 1) / 2 + k];
            a[i * (i + 1) / 2 + j] = s2 * inv;
        }
    }

    // invert lower triangular in place
#pragma unroll
    for (int j = 0; j < GS; j++) {
        a[j * (j + 1) / 2 + j] = 1.0f / a[j * (j + 1) / 2 + j];
#pragma unroll
        for (int i = j + 1; i < GS; i++) {
            float s2 = 0.0f;
#pragma unroll
            for (int k = j; k < i; k++)
                s2 += a[i * (i + 1) / 2 + k] * a[k * (k + 1) / 2 + j];
            a[i * (i + 1) / 2 + j] = -s2 / a[i * (i + 1) / 2 + i];
        }
    }

    // W (full, zero upper), bias b = W * mu
#pragma unroll
    for (int i = 0; i < GS; i++) {
        float bb = 0.0f;
#pragma unroll
        for (int j = 0; j < GS; j++) {
            float w = (j <= i) ? a[i * (i + 1) / 2 + j] : 0.0f;
            g_W[g][i * GS + j] = w;
            bb += w * mu[j];
        }
        g_b[g][i] = bb;
    }
}

// ---------------------------------------------------------------------------
// apply: out[i] = sum_j W[i][j]*x[j] - b[i], streaming-accumulator form.
// grid = (NGRP, APPLY_BY), block 256, 2 blocks/SM.
// ---------------------------------------------------------------------------
__global__ void __launch_bounds__(256, 2) apply_kernel(const float* __restrict__ x,
                                                       float* __restrict__ out) {
    const int g   = blockIdx.x;
    const int tid = threadIdx.x;

    __shared__ float Ws[GS * GS];
    __shared__ float bs[GS];
    Ws[tid & 255] = g_W[g][tid & 255];
    if (tid < GS) bs[tid] = g_b[g][tid];
    __syncthreads();

    const float4* x4 = (const float4*)x;
    float4*       o4 = (float4*)out;
    const int step = APPLY_BY * 256;

    for (int pos = blockIdx.y * 256 + tid; pos < NPOS4; pos += step) {
        const int m = pos / HW4;
        const int q = pos - m * HW4;
        const size_t base = ((size_t)m * D_FEAT + (size_t)g * GS) * HW4 + q;

        float4 acc[GS];
#pragma unroll
        for (int i = 0; i < GS; i++) {
            float bi = bs[i];
            acc[i] = make_float4(-bi, -bi, -bi, -bi);
        }

        float4 vn = x4[base];
#pragma unroll
        for (int c = 0; c < GS; c++) {
            float4 v = vn;
            if (c < GS - 1) vn = x4[base + (size_t)(c + 1) * HW4];
#pragma unroll
            for (int i = c; i < GS; i++) {
                float w = Ws[i * GS + c];
                acc[i].x += w * v.x;
                acc[i].y += w * v.y;
                acc[i].z += w * v.z;
                acc[i].w += w * v.w;
            }
            o4[base + (size_t)c * HW4] = acc[c];
        }
    }
}

// ---------------------------------------------------------------------------
extern "C" void kernel_launch(void* const* d_in, const int* in_sizes, int n_in,
                              void* d_out, int out_size) {
    const float* x = (const float*)d_in[0];
    float* out = (float*)d_out;

    zero_kernel<<<1, 256>>>();
    stats_kernel<<<dim3(NGRP, STATS_BY), 256>>>(x);
    solve_kernel<<<1, 32>>>();
    apply_kernel<<<dim3(NGRP, APPLY_BY), 256>>>(x, out);
}

// round 3
// speedup vs baseline: 1.5015x; 1.3112x over previous
#include <cuda_runtime.h>
#include <cuda_bf16.h>
#include <math.h>

#define M_BATCH   32
#define D_FEAT    256
#define HW        3136
#define HW4       784
#define NGRP      16
#define GS        16
#define NPOS      100352          // samples per channel
#define NPOS4     25088           // float4 positions per channel
#define PAIRS     136
#define EPS_W     1e-6f

#define STATS_BY  18
#define APPLY_BY  18
#define TILE      64              // float4 positions per smem tile
#define CHUNK     1394            // ceil(NPOS4 / STATS_BY)
#define NTILES    22              // ceil(CHUNK / TILE)

// Scratch (per-block partials: fully overwritten each launch -> no zeroing)
__device__ float g_psum[NGRP][STATS_BY][GS];
__device__ float g_pprod[NGRP][STATS_BY][PAIRS];
__device__ float g_W[NGRP][GS * GS];
__device__ float g_b[NGRP][GS];          // W * mu

__device__ __forceinline__ float warp_sum(float v) {
    v += __shfl_down_sync(0xffffffffu, v, 16);
    v += __shfl_down_sync(0xffffffffu, v, 8);
    v += __shfl_down_sync(0xffffffffu, v, 4);
    v += __shfl_down_sync(0xffffffffu, v, 2);
    v += __shfl_down_sync(0xffffffffu, v, 1);
    return v;
}

// ---------------------------------------------------------------------------
// stats: smem-staged, double-buffered. Global data read exactly once.
// Block 256 thr. grid = (NGRP, STATS_BY).
// Roles (2 warps = 64 threads each, one float4-position per thread per tile):
//   role 0: lower-tri of ch 0-7   (36 acc) + sums 0-7
//   role 1: rows 8-15 x cols 0-3  (32 acc)
//   role 2: rows 8-15 x cols 4-7  (32 acc)
//   role 3: lower-tri of ch 8-15  (36 acc) + sums 8-15
// ---------------------------------------------------------------------------
__global__ void __launch_bounds__(256, 2) stats_kernel(const float4* __restrict__ x4) {
    const int g   = blockIdx.x;
    const int by  = blockIdx.y;
    const int tid = threadIdx.x;

    const int P0 = by * CHUNK;
    const int P1 = (P0 + CHUNK < NPOS4) ? (P0 + CHUNK) : NPOS4;

    __shared__ float4 sbuf[2][GS * TILE];          // 2 x 16KB
    __shared__ float rsum[GS];
    __shared__ float rpair[PAIRS];
    for (int i = tid; i < GS; i += 256) rsum[i] = 0.0f;
    for (int i = tid; i < PAIRS; i += 256) rpair[i] = 0.0f;

    const int li  = tid & 63;          // load position within tile
    const int c0  = (tid >> 6) * 4;    // 4 channels per loader thread
    const int gch = g * GS;

    const int role = tid >> 6;         // 0..3 (2 warps each)
    const int ri   = tid & 63;         // position within tile for compute

    float acc[44];
#pragma unroll
    for (int i = 0; i < 44; i++) acc[i] = 0.0f;

    float4 r[4];

    // ---- prologue: load tile 0 into sbuf[0]
    {
        const int pos = P0 + li;
        if (pos < P1) {
            const int m = pos / HW4;
            const int q = pos - m * HW4;
            const int base = (m * D_FEAT + gch) * HW4 + q;
#pragma unroll
            for (int j = 0; j < 4; j++) r[j] = x4[base + (c0 + j) * HW4];
        } else {
#pragma unroll
            for (int j = 0; j < 4; j++) r[j] = make_float4(0.f, 0.f, 0.f, 0.f);
        }
#pragma unroll
        for (int j = 0; j < 4; j++) sbuf[0][(c0 + j) * TILE + li] = r[j];
    }
    __syncthreads();

    for (int t = 0; t < NTILES; t++) {
        // issue loads for tile t+1 (latency hidden by compute below)
        if (t + 1 < NTILES) {
            const int pos = P0 + (t + 1) * TILE + li;
            if (pos < P1) {
                const int m = pos / HW4;
                const int q = pos - m * HW4;
                const int base = (m * D_FEAT + gch) * HW4 + q;
#pragma unroll
                for (int j = 0; j < 4; j++) r[j] = x4[base + (c0 + j) * HW4];
            } else {
#pragma unroll
                for (int j = 0; j < 4; j++) r[j] = make_float4(0.f, 0.f, 0.f, 0.f);
            }
        }

        // compute from sbuf[t&1]
        const float4* Bf = sbuf[t & 1];
        if (role == 0) {
            float4 v[8];
#pragma unroll
            for (int c = 0; c < 8; c++) v[c] = Bf[c * TILE + ri];
            int k = 0;
#pragma unroll
            for (int i = 0; i < 8; i++)
#pragma unroll
                for (int j = 0; j <= i; j++) {
                    acc[k] += v[i].x * v[j].x; acc[k] += v[i].y * v[j].y;
                    acc[k] += v[i].z * v[j].z; acc[k] += v[i].w * v[j].w;
                    k++;
                }
#pragma unroll
            for (int c = 0; c < 8; c++)
                acc[36 + c] += (v[c].x + v[c].y) + (v[c].z + v[c].w);
        } else if (role == 3) {
            float4 v[8];
#pragma unroll
            for (int c = 0; c < 8; c++) v[c] = Bf[(c + 8) * TILE + ri];
            int k = 0;
#pragma unroll
            for (int i = 0; i < 8; i++)
#pragma unroll
                for (int j = 0; j <= i; j++) {
                    acc[k] += v[i].x * v[j].x; acc[k] += v[i].y * v[j].y;
                    acc[k] += v[i].z * v[j].z; acc[k] += v[i].w * v[j].w;
                    k++;
                }
#pragma unroll
            for (int c = 0; c < 8; c++)
                acc[36 + c] += (v[c].x + v[c].y) + (v[c].z + v[c].w);
        } else {
            const int cb = (role == 1) ? 0 : 4;
            float4 vh[8], vc[4];
#pragma unroll
            for (int c = 0; c < 8; c++) vh[c] = Bf[(c + 8) * TILE + ri];
#pragma unroll
            for (int c = 0; c < 4; c++) vc[c] = Bf[(cb + c) * TILE + ri];
#pragma unroll
            for (int i = 0; i < 8; i++)
#pragma unroll
                for (int j = 0; j < 4; j++) {
                    const int k = i * 4 + j;
                    acc[k] += vh[i].x * vc[j].x; acc[k] += vh[i].y * vc[j].y;
                    acc[k] += vh[i].z * vc[j].z; acc[k] += vh[i].w * vc[j].w;
                }
        }

        // stage tile t+1 into the other buffer (safe: its readers finished at
        // the sync that ended iteration t-1)
        if (t + 1 < NTILES) {
#pragma unroll
            for (int j = 0; j < 4; j++)
                sbuf[(t + 1) & 1][(c0 + j) * TILE + li] = r[j];
        }
        __syncthreads();
    }

    // ---- reduction: warp shuffle -> shared atomics -> per-block partials
    const int lane = tid & 31;
    if (role == 0) {
#pragma unroll
        for (int k = 0; k < 36; k++) {
            float v = warp_sum(acc[k]);
            if (lane == 0) atomicAdd(&rpair[k], v);
        }
#pragma unroll
        for (int c = 0; c < 8; c++) {
            float v = warp_sum(acc[36 + c]);
            if (lane == 0) atomicAdd(&rsum[c], v);
        }
    } else if (role == 3) {
        int k = 0;
#pragma unroll
        for (int i = 0; i < 8; i++)
#pragma unroll
            for (int j = 0; j <= i; j++) {
                float v = warp_sum(acc[k]);
                if (lane == 0) {
                    const int r2 = i + 8, c2 = j + 8;
                    atomicAdd(&rpair[r2 * (r2 + 1) / 2 + c2], v);
                }
                k++;
            }
#pragma unroll
        for (int c = 0; c < 8; c++) {
            float v = warp_sum(acc[36 + c]);
            if (lane == 0) atomicAdd(&rsum[8 + c], v);
        }
    } else {
        const int cb = (role == 1) ? 0 : 4;
#pragma unroll
        for (int i = 0; i < 8; i++)
#pragma unroll
            for (int j = 0; j < 4; j++) {
                float v = warp_sum(acc[i * 4 + j]);
                if (lane == 0) {
                    const int r2 = i + 8;
                    atomicAdd(&rpair[r2 * (r2 + 1) / 2 + cb + j], v);
                }
            }
    }
    __syncthreads();

    for (int i = tid; i < PAIRS; i += 256) g_pprod[g][by][i] = rpair[i];
    if (tid < GS) g_psum[g][by][tid] = rsum[tid];
}

// ---------------------------------------------------------------------------
// solve: one warp per group. Reduce partials, sigma, column-parallel Cholesky,
// column-parallel triangular inverse, emit W and b = W*mu.
// ---------------------------------------------------------------------------
__global__ void solve_kernel() {
    const int tid  = threadIdx.x;     // 512
    const int g    = tid >> 5;
    const int lane = tid & 31;

    __shared__ float A [NGRP][GS][GS + 1];
    __shared__ float Wm[NGRP][GS][GS + 1];
    __shared__ float MU[NGRP][GS];

    const float n   = (float)NPOS;
    const float nm1 = (float)(NPOS - 1);

    if (lane < GS) {
        float s = 0.0f;
#pragma unroll
        for (int by = 0; by < STATS_BY; by++) s += g_psum[g][by][lane];
        MU[g][lane] = s / n;
    }
    __syncwarp();

    for (int k = lane; k < PAIRS; k += 32) {
        int i = (int)((sqrtf(8.0f * k + 1.0f) - 1.0f) * 0.5f);
        while ((i + 1) * (i + 2) / 2 <= k) i++;
        while (i * (i + 1) / 2 > k) i--;
        const int j = k - i * (i + 1) / 2;
        float s = 0.0f;
#pragma unroll
        for (int by = 0; by < STATS_BY; by++) s += g_pprod[g][by][k];
        float cv = (s - n * MU[g][i] * MU[g][j]) / nm1;
        cv *= (1.0f - EPS_W);
        if (i == j) cv += EPS_W;
        A[g][i][j] = cv;
    }
    __syncwarp();

    // right-looking Cholesky, lanes 0-15 active
    for (int j = 0; j < GS; j++) {
        if (lane == j) A[g][j][j] = sqrtf(A[g][j][j]);
        __syncwarp();
        const float dinv = 1.0f / A[g][j][j];
        if (lane > j && lane < GS) A[g][lane][j] *= dinv;
        __syncwarp();
        if (lane > j && lane < GS) {
            const float lij = A[g][lane][j];
            for (int k2 = j + 1; k2 <= lane; k2++)
                A[g][lane][k2] -= lij * A[g][k2][j];
        }
        __syncwarp();
    }

    // triangular inverse: lane j computes column j
    if (lane < GS) {
        const int j = lane;
        Wm[g][j][j] = 1.0f / A[g][j][j];
        for (int i = j + 1; i < GS; i++) {
            float s = 0.0f;
            for (int k2 = j; k2 < i; k2++) s += A[g][i][k2] * Wm[g][k2][j];
            Wm[g][i][j] = -s / A[g][i][i];
        }
    }
    __syncwarp();

    if (lane < GS) {
        float bb = 0.0f;
        for (int j = 0; j <= lane; j++) bb += Wm[g][lane][j] * MU[g][j];
        g_b[g][lane] = bb;
    }
    for (int e = lane; e < GS * GS; e += 32) {
        const int i = e >> 4, j = e & 15;
        g_W[g][e] = (j <= i) ? Wm[g][i][j] : 0.0f;
    }
}

// ---------------------------------------------------------------------------
// apply: batched 16 loads (MLP 16), per-row acc, bias fold.
// grid = (NGRP, APPLY_BY), block 256, 2 blocks/SM.
// ---------------------------------------------------------------------------
__global__ void __launch_bounds__(256, 2) apply_kernel(const float4* __restrict__ x4,
                                                       float4* __restrict__ o4) {
    const int g   = blockIdx.x;
    const int tid = threadIdx.x;

    __shared__ float Ws[GS * GS];
    __shared__ float bs[GS];
    Ws[tid] = g_W[g][tid];           // blockDim == 256 == GS*GS
    if (tid < GS) bs[tid] = g_b[g][tid];
    __syncthreads();

    const int step = APPLY_BY * 256;
    for (int pos = blockIdx.y * 256 + tid; pos < NPOS4; pos += step) {
        const int m = pos / HW4;
        const int q = pos - m * HW4;
        const int base = (m * D_FEAT + g * GS) * HW4 + q;

        float4 v[GS];
#pragma unroll
        for (int c = 0; c < GS; c++) v[c] = x4[base + c * HW4];

#pragma unroll
        for (int i = 0; i < GS; i++) {
            const float bi = bs[i];
            float4 a = make_float4(-bi, -bi, -bi, -bi);
#pragma unroll
            for (int j = 0; j <= i; j++) {
                const float w = Ws[i * GS + j];
                a.x += w * v[j].x; a.y += w * v[j].y;
                a.z += w * v[j].z; a.w += w * v[j].w;
            }
            o4[base + i * HW4] = a;
        }
    }
}

// ---------------------------------------------------------------------------
extern "C" void kernel_launch(void* const* d_in, const int* in_sizes, int n_in,
                              void* d_out, int out_size) {
    const float4* x = (const float4*)d_in[0];
    float4* out = (float4*)d_out;

    stats_kernel<<<dim3(NGRP, STATS_BY), 256>>>(x);
    solve_kernel<<<1, 512>>>();
    apply_kernel<<<dim3(NGRP, APPLY_BY), 256>>>(x, out);
}